// round 15
// baseline (speedup 1.0000x reference)
#include <cuda_runtime.h>
#include <cuda_bf16.h>
#include <cstdint>

// ---------------------------------------------------------------------------
// GemNetTDecoder — R15: R14 champion + gatemsg split along N into 2 half-CTAs
// (64 accumulators, 57 KB smem) so it runs at 2 CTAs/SM like the edge GEMM.
// ---------------------------------------------------------------------------

#define PI_F 3.14159265358979323846f

constexpr int NCRYST = 256;
constexpr int AA     = 64;
constexpr int KNB    = 20;
constexpr int HIDC   = 128;
constexpr int LATC   = 256;
constexpr int NATOMS = NCRYST * AA;       // 16384
constexpr int NEDGE  = NATOMS * KNB;      // 327680
constexpr float FCUT = 6.0f;
constexpr float DELTA = FCUT / 127.0f;

constexpr size_t EH = (size_t)NEDGE * HIDC;

constexpr int WOFF_EDGE = 0;
constexpr int WOFF_RBF  = 49152;
constexpr int WOFF_MSG  = 98304;
constexpr int WOFF_UPD  = 147456;
constexpr int WTOT      = 294912;

// --------------------------- device scratch -------------------------------
__device__ float g_dist[NEDGE];
__device__ float g_unit[NEDGE * 3];
__device__ float g_h[NATOMS * HIDC];
__device__ __nv_bfloat16 g_h_hi[NATOMS * HIDC];
__device__ __nv_bfloat16 g_h_lo[NATOMS * HIDC];
__device__ __nv_bfloat16 g_m_hi[EH];
__device__ __nv_bfloat16 g_m_lo[EH];
__device__ float g_agg[NATOMS * HIDC];
__device__ __nv_bfloat16 g_wt_hi[WTOT];
__device__ __nv_bfloat16 g_wt_lo[WTOT];

// --------------------------- helpers ---------------------------------------
__device__ __forceinline__ uint32_t smem_u32(const void* p) {
    uint32_t a;
    asm("{ .reg .u64 t; cvta.to.shared.u64 t, %1; cvt.u32.u64 %0, t; }"
        : "=r"(a) : "l"(p));
    return a;
}
__device__ __forceinline__ void ldm4(uint32_t* r, uint32_t a) {
    asm volatile("ldmatrix.sync.aligned.m8n8.x4.shared.b16 {%0,%1,%2,%3}, [%4];"
                 : "=r"(r[0]), "=r"(r[1]), "=r"(r[2]), "=r"(r[3]) : "r"(a));
}
__device__ __forceinline__ void mma16816(float* c, const uint32_t* a,
                                         const uint32_t* b) {
    asm volatile(
        "mma.sync.aligned.m16n8k16.row.col.f32.bf16.bf16.f32 "
        "{%0,%1,%2,%3}, {%4,%5,%6,%7}, {%8,%9}, {%0,%1,%2,%3};"
        : "+f"(c[0]), "+f"(c[1]), "+f"(c[2]), "+f"(c[3])
        : "r"(a[0]), "r"(a[1]), "r"(a[2]), "r"(a[3]), "r"(b[0]), "r"(b[1]));
}
__device__ __forceinline__ void cp16(uint32_t dst, const void* src) {
    asm volatile("cp.async.cg.shared.global [%0], [%1], 16;"
                 :: "r"(dst), "l"(src) : "memory");
}
__device__ __forceinline__ void cp_commit() {
    asm volatile("cp.async.commit_group;" ::: "memory");
}
__device__ __forceinline__ void cp_wait0() {
    asm volatile("cp.async.wait_group 0;" ::: "memory");
}
__device__ __forceinline__ uint32_t pack_bf(__nv_bfloat16 a, __nv_bfloat16 b) {
    return (uint32_t)__bfloat16_as_ushort(a) |
           ((uint32_t)__bfloat16_as_ushort(b) << 16);
}
__device__ __forceinline__ void split2(float v0, float v1, uint32_t& hi,
                                       uint32_t& lo) {
    __nv_bfloat16 h0 = __float2bfloat16(v0), h1 = __float2bfloat16(v1);
    hi = pack_bf(h0, h1);
    lo = pack_bf(__float2bfloat16(v0 - __bfloat162float(h0)),
                 __float2bfloat16(v1 - __bfloat162float(h1)));
}
__device__ __forceinline__ float bf2sum(uint32_t hi, uint32_t lo, int half) {
    uint16_t h = half ? (uint16_t)(hi >> 16) : (uint16_t)(hi & 0xffff);
    uint16_t l = half ? (uint16_t)(lo >> 16) : (uint16_t)(lo & 0xffff);
    return __bfloat162float(__ushort_as_bfloat16(h)) +
           __bfloat162float(__ushort_as_bfloat16(l));
}

constexpr int STR   = 72;
constexpr int TILEB = 128 * STR * 2;      // 18432

// ---- edge gemm smem geometry ----
constexpr int EA4_HI = 0;
constexpr int EA4_LO = TILEB;
constexpr int EA5_HI = 2 * TILEB;
constexpr int EA5_LO = 3 * TILEB;
constexpr int EB_HI  = 4 * TILEB;
constexpr int EB_LO  = 5 * TILEB;
constexpr int EEND   = 6 * TILEB;
constexpr int E_BIAS = EEND;
constexpr int E_SRC  = E_BIAS + 512;
constexpr int E_DST  = E_SRC + 512;
constexpr int E_DIST = E_DST + 512;
constexpr int E_WF   = E_DIST + 512;
constexpr int E_FRC  = E_WF + 512;
constexpr int SMB_EDGE = E_FRC + 512;     // 113664

// ---- gatemsg (N-split) smem geometry: A 128x64, B 64x64, single stage ----
constexpr int G2A_HI = 0;                 // 18432
constexpr int G2A_LO = TILEB;
constexpr int G2B_HI = 2 * TILEB;         // 64 x 144 = 9216
constexpr int G2B_LO = 2 * TILEB + 9216;
constexpr int G2END  = 2 * TILEB + 18432; // 55296
constexpr int G2_BIAS = G2END;
constexpr int G2_DST  = G2_BIAS + 512;
constexpr int G2_DIST = G2_DST + 512;
constexpr int SMB_GM2 = G2_DIST + 512;    // 56832 (2 CTAs/SM: 113664)

// ---- fc_fused smem geometry ----
constexpr int F_XS = 0;
constexpr int F_WS = 4352;
constexpr int F_A1 = 12544;
constexpr int F_A2 = 46336;
constexpr int SMB_FC = 80128;

// Generate rbf tile (cols [kc2, kc2+64)) into the given smem hi/lo planes.
__device__ __forceinline__ void gen_rbf(char* smp, int off_hi, int off_lo,
                                        const float* sdist, int kc2, int tid) {
    uint4 z4 = make_uint4(0, 0, 0, 0);
#pragma unroll
    for (int i = 0; i < 9; i++) {
        int lin = i * 256 + tid;
        if (lin < 2304) {
            int plane = lin >= 1152;
            int j = plane ? lin - 1152 : lin;
            *(uint4*)(smp + (plane ? off_lo : off_hi) + j * 16) = z4;
        }
    }
    __syncthreads();
    if (tid < 128) {
        float d = sdist[tid];
        if (d < FCUT) {
            float env = 0.5f * (cosf(PI_F * d * (1.f / FCUT)) + 1.f);
            float t = d * (1.f / DELTA);
            int klo = max(kc2, (int)ceilf(t) - 6);
            int khi = min(kc2 + 63, (int)floorf(t) + 6);
            for (int k = klo; k <= khi; k++) {
                float x = t - (float)k;
                float v = __expf(-x * x) * env;
                __nv_bfloat16 h = __float2bfloat16(v);
                __nv_bfloat16 l = __float2bfloat16(v - __bfloat162float(h));
                int boff = tid * 144 + (k - kc2) * 2;
                *(__nv_bfloat16*)(smp + off_hi + boff) = h;
                *(__nv_bfloat16*)(smp + off_lo + boff) = l;
            }
        }
    }
}

// --------------------------- fused geometry --------------------------------
__global__ __launch_bounds__(256) void geo_k(
    const float* __restrict__ lengths, const float* __restrict__ angles,
    const float* __restrict__ frac, const int* __restrict__ src,
    const int* __restrict__ dst) {
    __shared__ float sc[AA][3];
    int c = blockIdx.x, tid = threadIdx.x;
    float r0 = angles[c * 3 + 0] * (PI_F / 180.f);
    float r1 = angles[c * 3 + 1] * (PI_F / 180.f);
    float r2 = angles[c * 3 + 2] * (PI_F / 180.f);
    float c0 = cosf(r0), c1 = cosf(r1), c2 = cosf(r2), sg = sinf(r2);
    float a = lengths[c * 3 + 0], b = lengths[c * 3 + 1], cc = lengths[c * 3 + 2];
    float cx = cc * c1;
    float cy = cc * (c0 - c1 * c2) / sg;
    float cz = sqrtf(fmaxf(cc * cc - cx * cx - cy * cy, 1e-8f));
    if (tid < AA) {
        int atom = c * AA + tid;
        float f0 = frac[atom * 3 + 0], f1 = frac[atom * 3 + 1],
              f2 = frac[atom * 3 + 2];
        sc[tid][0] = f0 * a + f1 * (b * c2) + f2 * cx;
        sc[tid][1] = f1 * (b * sg) + f2 * cy;
        sc[tid][2] = f2 * cz;
    }
    __syncthreads();
#pragma unroll
    for (int i = 0; i < 5; i++) {
        int el = i * 256 + tid;
        int e = c * (AA * KNB) + el;
        int s = src[e] & 63, d = dst[e] & 63;
        float dx = sc[d][0] - sc[s][0];
        float dy = sc[d][1] - sc[s][1];
        float dz = sc[d][2] - sc[s][2];
        float dist = sqrtf(dx * dx + dy * dy + dz * dz + 1e-12f);
        g_dist[e] = dist;
        float inv = 1.f / dist;
        g_unit[e * 3 + 0] = dx * inv;
        g_unit[e * 3 + 1] = dy * inv;
        g_unit[e * 3 + 2] = dz * inv;
    }
}

// --------------------------- merged weight prep ----------------------------
__global__ __launch_bounds__(256) void wprep_all(
    const float* __restrict__ We, const float* __restrict__ Wr,
    const float* __restrict__ Wm, const float* __restrict__ Wu) {
    int blk = blockIdx.x;
    const float* W;
    int K, base, lb;
    if (blk < 192)      { W = We; K = 384; base = WOFF_EDGE; lb = blk; }
    else if (blk < 384) { W = Wr; K = 128; base = WOFF_RBF;  lb = blk - 192; }
    else if (blk < 576) { W = Wm; K = 128; base = WOFF_MSG;  lb = blk - 384; }
    else                { W = Wu; K = 384; base = WOFF_UPD;  lb = blk - 576; }
    int idx = lb * 256 + threadIdx.x;
    int m = idx / (K * 128);
    int r = idx - m * (K * 128);
    int k = r >> 7, n = r & 127;
    float v = W[idx];
    __nv_bfloat16 h = __float2bfloat16(v);
    size_t o = (size_t)base + (size_t)m * K * 128 + (size_t)n * K + k;
    g_wt_hi[o] = h;
    g_wt_lo[o] = __float2bfloat16(v - __bfloat162float(h));
}

__global__ void zero_agg_k(float* __restrict__ outp) {
    int i = blockIdx.x * 256 + threadIdx.x;
    *(float4*)&g_agg[(size_t)i * 4] = make_float4(0.f, 0.f, 0.f, 0.f);
    if (i * 4 < NATOMS * 3)
        *(float4*)&outp[(size_t)i * 4] = make_float4(0.f, 0.f, 0.f, 0.f);
}

// --------------------------- fp32 SIMT gemm (small) ------------------------
template <int MODE, int KDIM, int EPI, int SPLIT, int ZAGG>
__global__ __launch_bounds__(256) void gemm_k(
    const float* __restrict__ X, const float* __restrict__ W,
    const float* __restrict__ bias, const float* __restrict__ base,
    float* __restrict__ out, __nv_bfloat16* __restrict__ outhi,
    __nv_bfloat16* __restrict__ outlo, float* __restrict__ zbuf,
    const float* __restrict__ emb, const float* __restrict__ z,
    const int* __restrict__ atype) {
    __shared__ float Xs[16][68];
    __shared__ float Ws[16][128];
    __shared__ int sat[64];

    int row0 = blockIdx.x * 64;
    int tid = threadIdx.x;
    if (MODE == 1) {
        if (tid < 64) sat[tid] = atype[row0 + tid];
        __syncthreads();
    }

    int c0 = (tid & 15) * 8;
    int r0 = (tid >> 4) * 4;
    float acc[4][8];
#pragma unroll
    for (int i = 0; i < 4; i++)
#pragma unroll
        for (int j = 0; j < 8; j++) acc[i][j] = 0.f;

    for (int k0 = 0; k0 < KDIM; k0 += 16) {
#pragma unroll
        for (int t = 0; t < 4; t++) {
            int lin = tid * 4 + t;
            int r = lin >> 4, kk = lin & 15;
            int k = k0 + kk;
            float v;
            if (MODE == 0) {
                v = X[(size_t)(row0 + r) * KDIM + k];
            } else {
                v = (k < 128) ? emb[sat[r] * 128 + k]
                              : z[(size_t)((row0 + r) >> 6) * LATC + (k - 128)];
            }
            Xs[kk][r] = v;
        }
#pragma unroll
        for (int t = 0; t < 2; t++) {
            int i4 = tid + t * 256;
            int kk = i4 >> 5, n = (i4 & 31) * 4;
            *(float4*)&Ws[kk][n] = *(const float4*)&W[(size_t)(k0 + kk) * 128 + n];
        }
        __syncthreads();
#pragma unroll
        for (int kk = 0; kk < 16; kk++) {
            float4 a  = *(const float4*)&Xs[kk][r0];
            float4 b0 = *(const float4*)&Ws[kk][c0];
            float4 b1 = *(const float4*)&Ws[kk][c0 + 4];
            float av[4] = {a.x, a.y, a.z, a.w};
            float bv[8] = {b0.x, b0.y, b0.z, b0.w, b1.x, b1.y, b1.z, b1.w};
#pragma unroll
            for (int i = 0; i < 4; i++)
#pragma unroll
                for (int j = 0; j < 8; j++) acc[i][j] += av[i] * bv[j];
        }
        __syncthreads();
    }

    float bv[8];
    {
        float4 q0 = *(const float4*)&bias[c0];
        float4 q1 = *(const float4*)&bias[c0 + 4];
        bv[0] = q0.x; bv[1] = q0.y; bv[2] = q0.z; bv[3] = q0.w;
        bv[4] = q1.x; bv[5] = q1.y; bv[6] = q1.z; bv[7] = q1.w;
    }
#pragma unroll
    for (int i = 0; i < 4; i++) {
        size_t off = (size_t)(row0 + r0 + i) * 128 + c0;
        float v[8];
#pragma unroll
        for (int j = 0; j < 8; j++) v[j] = fmaxf(acc[i][j] + bv[j], 0.f);
        if (EPI == 3) {
            float4 bb0 = *(const float4*)&base[off];
            float4 bb1 = *(const float4*)&base[off + 4];
            v[0] += bb0.x; v[1] += bb0.y; v[2] += bb0.z; v[3] += bb0.w;
            v[4] += bb1.x; v[5] += bb1.y; v[6] += bb1.z; v[7] += bb1.w;
        }
        float4 o0 = {v[0], v[1], v[2], v[3]};
        float4 o1 = {v[4], v[5], v[6], v[7]};
        *(float4*)&out[off] = o0;
        *(float4*)&out[off + 4] = o1;
        if (SPLIT) {
            uint32_t hh[4], ll[4];
#pragma unroll
            for (int q = 0; q < 4; q++) split2(v[2 * q], v[2 * q + 1], hh[q], ll[q]);
            *(uint4*)&outhi[off] = make_uint4(hh[0], hh[1], hh[2], hh[3]);
            *(uint4*)&outlo[off] = make_uint4(ll[0], ll[1], ll[2], ll[3]);
        }
        if (ZAGG) {
            float4 zz = {0.f, 0.f, 0.f, 0.f};
            *(float4*)&zbuf[off] = zz;
            *(float4*)&zbuf[off + 4] = zz;
        }
    }
}

// --------------------------- fused fc1+fc2+fc3 -----------------------------
__global__ __launch_bounds__(256) void fc_fused(
    const float* __restrict__ W1, const float* __restrict__ b1,
    const float* __restrict__ W2, const float* __restrict__ b2,
    const float* __restrict__ W3, const float* __restrict__ b3,
    float* __restrict__ out) {
    extern __shared__ char sm[];
    float (*Xs)[68]  = (float(*)[68])(sm + F_XS);
    float (*Ws)[128] = (float(*)[128])(sm + F_WS);
    float* A1 = (float*)(sm + F_A1);
    float* A2 = (float*)(sm + F_A2);

    int row0 = blockIdx.x * 64;
    int tid = threadIdx.x;
    int c0 = (tid & 15) * 8;
    int r0 = (tid >> 4) * 4;

#pragma unroll
    for (int phase = 0; phase < 2; phase++) {
        const float* W = phase ? W2 : W1;
        const float* bias = phase ? b2 : b1;
        float* dstA = phase ? A2 : A1;
        float acc[4][8];
#pragma unroll
        for (int i = 0; i < 4; i++)
#pragma unroll
            for (int j = 0; j < 8; j++) acc[i][j] = 0.f;
        for (int k0 = 0; k0 < 128; k0 += 16) {
#pragma unroll
            for (int t = 0; t < 4; t++) {
                int lin = tid * 4 + t;
                int r = lin >> 4, kk = lin & 15;
                float v = phase ? A1[r * 132 + k0 + kk]
                                : g_h[(size_t)(row0 + r) * 128 + k0 + kk];
                Xs[kk][r] = v;
            }
#pragma unroll
            for (int t = 0; t < 2; t++) {
                int i4 = tid + t * 256;
                int kk = i4 >> 5, n = (i4 & 31) * 4;
                *(float4*)&Ws[kk][n] =
                    *(const float4*)&W[(size_t)(k0 + kk) * 128 + n];
            }
            __syncthreads();
#pragma unroll
            for (int kk = 0; kk < 16; kk++) {
                float4 a  = *(const float4*)&Xs[kk][r0];
                float4 b0 = *(const float4*)&Ws[kk][c0];
                float4 b1v = *(const float4*)&Ws[kk][c0 + 4];
                float av[4] = {a.x, a.y, a.z, a.w};
                float bv[8] = {b0.x, b0.y, b0.z, b0.w, b1v.x, b1v.y, b1v.z, b1v.w};
#pragma unroll
                for (int i = 0; i < 4; i++)
#pragma unroll
                    for (int j = 0; j < 8; j++) acc[i][j] += av[i] * bv[j];
            }
            __syncthreads();
        }
        float bv[8];
        {
            float4 q0 = *(const float4*)&bias[c0];
            float4 q1 = *(const float4*)&bias[c0 + 4];
            bv[0] = q0.x; bv[1] = q0.y; bv[2] = q0.z; bv[3] = q0.w;
            bv[4] = q1.x; bv[5] = q1.y; bv[6] = q1.z; bv[7] = q1.w;
        }
#pragma unroll
        for (int i = 0; i < 4; i++)
#pragma unroll
            for (int j = 0; j < 8; j++)
                dstA[(r0 + i) * 132 + c0 + j] = fmaxf(acc[i][j] + bv[j], 0.f);
        __syncthreads();
    }

    if (tid < 128) {
        int row = tid >> 1;
        int col = tid & 1;
        float s = 0.f;
#pragma unroll 16
        for (int k = 0; k < 128; k++) s += A2[row * 132 + k] * W3[k * 2 + col];
        out[(size_t)(row0 + row) * 2 + col] = s + b3[col];
    }
}

// --------------------------- mma.sync edge GEMM ----------------------------
template <int MODE, int FORCE>
__global__ __launch_bounds__(256, 2) void mma_edge_gemm(
    const __nv_bfloat16* __restrict__ wt_hi, const __nv_bfloat16* __restrict__ wt_lo,
    const float* __restrict__ bias, const int* __restrict__ srcp,
    const int* __restrict__ dstp, const float* __restrict__ Wf,
    const float* __restrict__ bf, float* __restrict__ outp) {
    extern __shared__ char sm[];
    uint32_t sbase = smem_u32(sm);
    float* sbias = (float*)(sm + E_BIAS);
    int* ssrc = (int*)(sm + E_SRC);
    int* sdst = (int*)(sm + E_DST);
    float* sdist = (float*)(sm + E_DIST);
    float* sWf = (float*)(sm + E_WF);
    float* sfrc = (float*)(sm + E_FRC);

    int tid = threadIdx.x;
    int row0 = blockIdx.x * 128;
    if (tid < 128) {
        ssrc[tid] = srcp[row0 + tid];
        sdst[tid] = dstp[row0 + tid];
        sbias[tid] = bias[tid];
        if (MODE == 2) sdist[tid] = g_dist[row0 + tid];
        if (FORCE) { sWf[tid] = Wf[tid]; sfrc[tid] = 0.f; }
    }
    __syncthreads();

    auto prefetch = [&](int c) {
        int kc = c * 64;
        int a_hi = (c == 5) ? EA5_HI : EA4_HI;
        int a_lo = (c == 5) ? EA5_LO : EA4_LO;
#pragma unroll
        for (int i = 0; i < 8; i++) {
            int lin = i * 256 + tid;
            int plane = lin >> 10;
            int idx = lin & 1023;
            int row = idx >> 3;
            int seg = idx & 7;
            if (!(MODE == 2 && c >= 4)) {
                const __nv_bfloat16* ap;
                if (c >= 4) {
                    ap = (plane ? g_m_lo : g_m_hi) +
                         (size_t)(row0 + row) * 128 + (kc - 256) + seg * 8;
                } else if (c < 2) {
                    ap = (plane ? g_h_lo : g_h_hi) + (size_t)ssrc[row] * 128 +
                         kc + seg * 8;
                } else {
                    ap = (plane ? g_h_lo : g_h_hi) + (size_t)sdst[row] * 128 +
                         (kc - 128) + seg * 8;
                }
                cp16(sbase + (plane ? a_lo : a_hi) + row * 144 + seg * 16, ap);
            }
            const __nv_bfloat16* bp =
                (plane ? wt_lo : wt_hi) + (size_t)row * 384 + kc + seg * 8;
            cp16(sbase + (plane ? EB_LO : EB_HI) + row * 144 + seg * 16, bp);
        }
        cp_commit();
    };

    int lane = tid & 31;
    int wm = (tid >> 5) & 3;
    int wn = tid >> 7;
    uint32_t a_row_l = (lane & 7) + ((lane >> 3) & 1) * 8;
    uint32_t a_k_l   = (lane >> 4) * 8;
    uint32_t b_n_l   = (lane & 7) + ((lane >> 4) & 1) * 8;
    uint32_t b_k_l   = ((lane >> 3) & 1) * 8;

    float acc[2][8][4];
#pragma unroll
    for (int i = 0; i < 2; i++)
#pragma unroll
        for (int j = 0; j < 8; j++)
#pragma unroll
            for (int q = 0; q < 4; q++) acc[i][j][q] = 0.f;

    for (int c = 0; c < 6; c++) {
        prefetch(c);
        if (MODE == 2 && c >= 4)
            gen_rbf(sm, (c == 5) ? EA5_HI : EA4_HI, (c == 5) ? EA5_LO : EA4_LO,
                    sdist, (c - 4) * 64, tid);
        cp_wait0();
        __syncthreads();
        uint32_t a_hi = sbase + ((c == 5) ? EA5_HI : EA4_HI);
        uint32_t a_lo = sbase + ((c == 5) ? EA5_LO : EA4_LO);
#pragma unroll
        for (int k16 = 0; k16 < 4; k16++) {
            uint32_t kk = k16 * 16;
            uint32_t ah[2][4], al[2][4];
#pragma unroll
            for (int mi = 0; mi < 2; mi++) {
                uint32_t off = (((uint32_t)(wm * 32 + mi * 16) + a_row_l) * STR +
                                kk + a_k_l) * 2;
                ldm4(ah[mi], a_hi + off);
                ldm4(al[mi], a_lo + off);
            }
#pragma unroll
            for (int p = 0; p < 4; p++) {
                uint32_t off = (((uint32_t)(wn * 64 + p * 16) + b_n_l) * STR +
                                kk + b_k_l) * 2;
                uint32_t r4[4], s4[4];
                ldm4(r4, sbase + EB_HI + off);
                ldm4(s4, sbase + EB_LO + off);
#pragma unroll
                for (int mi = 0; mi < 2; mi++) {
                    mma16816(acc[mi][2 * p],     ah[mi], &r4[0]);
                    mma16816(acc[mi][2 * p + 1], ah[mi], &r4[2]);
                    mma16816(acc[mi][2 * p],     ah[mi], &s4[0]);
                    mma16816(acc[mi][2 * p + 1], ah[mi], &s4[2]);
                    mma16816(acc[mi][2 * p],     al[mi], &r4[0]);
                    mma16816(acc[mi][2 * p + 1], al[mi], &r4[2]);
                }
            }
        }
        __syncthreads();
    }

    int rl_base = wm * 32 + (lane >> 2);
    int c_base = wn * 64 + (lane & 3) * 2;
    int resid_hi = wn ? EA5_HI : EA4_HI;
    int resid_lo = wn ? EA5_LO : EA4_LO;
    float rowpart[4] = {0.f, 0.f, 0.f, 0.f};
#pragma unroll
    for (int mi = 0; mi < 2; mi++)
#pragma unroll
        for (int nj = 0; nj < 8; nj++) {
            int rl = rl_base + mi * 16;
            int col = c_base + nj * 8;
            int lcol = col - wn * 64;
            float2 bb = *(const float2*)&sbias[col];
#pragma unroll
            for (int half = 0; half < 2; half++) {
                int row = rl + half * 8;
                size_t off = (size_t)(row0 + row) * 128 + col;
                float v0 = fmaxf(acc[mi][nj][half * 2 + 0] + bb.x, 0.f);
                float v1 = fmaxf(acc[mi][nj][half * 2 + 1] + bb.y, 0.f);
                if (MODE == 3) {
                    uint32_t oh = *(const uint32_t*)(sm + resid_hi +
                                                     row * 144 + lcol * 2);
                    uint32_t ol = *(const uint32_t*)(sm + resid_lo +
                                                     row * 144 + lcol * 2);
                    v0 += bf2sum(oh, ol, 0);
                    v1 += bf2sum(oh, ol, 1);
                }
                if (FORCE) {
                    rowpart[mi * 2 + half] += v0 * sWf[col] + v1 * sWf[col + 1];
                } else {
                    uint32_t hh, ll;
                    split2(v0, v1, hh, ll);
                    *(uint32_t*)&g_m_hi[off] = hh;
                    *(uint32_t*)&g_m_lo[off] = ll;
                }
            }
        }
    if (FORCE) {
#pragma unroll
        for (int q = 0; q < 4; q++) {
            int row = rl_base + (q >> 1) * 16 + (q & 1) * 8;
            atomicAdd(&sfrc[row], rowpart[q]);
        }
        __syncthreads();
        if (tid < 128) {
            float f = sfrc[tid] + bf[0];
            int d = sdst[tid];
            size_t ub = (size_t)(row0 + tid) * 3;
            atomicAdd(&outp[d * 3 + 0], f * g_unit[ub + 0]);
            atomicAdd(&outp[d * 3 + 1], f * g_unit[ub + 1]);
            atomicAdd(&outp[d * 3 + 2], f * g_unit[ub + 2]);
        }
    }
}

// --------------------------- gate*msg + segsum, N-split, 2 CTAs/SM ---------
// blockIdx.x = rowblock*2 + nh; CTA computes cols [nh*64, nh*64+64).
__global__ __launch_bounds__(256, 2) void mma_gatemsg(
    const __nv_bfloat16* __restrict__ wrbf_hi, const __nv_bfloat16* __restrict__ wrbf_lo,
    const __nv_bfloat16* __restrict__ wmsg_hi, const __nv_bfloat16* __restrict__ wmsg_lo,
    const float* __restrict__ bias, const int* __restrict__ dstp) {
    extern __shared__ char sm[];
    uint32_t sbase = smem_u32(sm);
    float* sbias = (float*)(sm + G2_BIAS);
    int* sdst = (int*)(sm + G2_DST);
    float* sdist = (float*)(sm + G2_DIST);

    int tid = threadIdx.x;
    int row0 = (blockIdx.x >> 1) * 128;
    int nh = blockIdx.x & 1;
    if (tid < 128) {
        sbias[tid] = bias[tid];
        sdst[tid] = dstp[row0 + tid] & 63;
        sdist[tid] = g_dist[row0 + tid];
    }
    __syncthreads();

    auto prefetch = [&](int c) {
        bool is_gate = (c < 2);
        int kc = (c & 1) * 64;
        const __nv_bfloat16* whi = is_gate ? wrbf_hi : wmsg_hi;
        const __nv_bfloat16* wlo = is_gate ? wrbf_lo : wmsg_lo;
        // B: 64 N-rows x 64 K
#pragma unroll
        for (int i = 0; i < 4; i++) {
            int lin = i * 256 + tid;
            int plane = lin >> 9;
            int idx = lin & 511;
            int n = idx >> 3;
            int seg = idx & 7;
            const __nv_bfloat16* bp =
                (plane ? wlo : whi) + (size_t)(nh * 64 + n) * 128 + kc + seg * 8;
            cp16(sbase + (plane ? G2B_LO : G2B_HI) + n * 144 + seg * 16, bp);
        }
        if (!is_gate) {
#pragma unroll
            for (int i = 0; i < 8; i++) {
                int lin = i * 256 + tid;
                int plane = lin >> 10;
                int idx = lin & 1023;
                int row = idx >> 3;
                int seg = idx & 7;
                const __nv_bfloat16* ap =
                    (plane ? g_m_lo : g_m_hi) + (size_t)(row0 + row) * 128 +
                    kc + seg * 8;
                cp16(sbase + (plane ? G2A_LO : G2A_HI) + row * 144 + seg * 16, ap);
            }
        }
        cp_commit();
    };

    int lane = tid & 31;
    int wm = (tid >> 5) & 3;
    int wn2 = tid >> 7;        // 2 N blocks of 32 cols
    uint32_t a_row_l = (lane & 7) + ((lane >> 3) & 1) * 8;
    uint32_t a_k_l   = (lane >> 4) * 8;
    uint32_t b_n_l   = (lane & 7) + ((lane >> 4) & 1) * 8;
    uint32_t b_k_l   = ((lane >> 3) & 1) * 8;

    float accg[2][4][4], accm[2][4][4];
#pragma unroll
    for (int i = 0; i < 2; i++)
#pragma unroll
        for (int j = 0; j < 4; j++)
#pragma unroll
            for (int q = 0; q < 4; q++) { accg[i][j][q] = 0.f; accm[i][j][q] = 0.f; }

    for (int c = 0; c < 4; c++) {
        bool is_gate = (c < 2);
        prefetch(c);
        if (is_gate)
            gen_rbf(sm, G2A_HI, G2A_LO, sdist, (c & 1) * 64, tid);
        cp_wait0();
        __syncthreads();
#pragma unroll
        for (int k16 = 0; k16 < 4; k16++) {
            uint32_t kk = k16 * 16;
            uint32_t ah[2][4], al[2][4];
#pragma unroll
            for (int mi = 0; mi < 2; mi++) {
                uint32_t off = (((uint32_t)(wm * 32 + mi * 16) + a_row_l) * STR +
                                kk + a_k_l) * 2;
                ldm4(ah[mi], sbase + G2A_HI + off);
                ldm4(al[mi], sbase + G2A_LO + off);
            }
#pragma unroll
            for (int p = 0; p < 2; p++) {
                uint32_t off = (((uint32_t)(wn2 * 32 + p * 16) + b_n_l) * STR +
                                kk + b_k_l) * 2;
                uint32_t r4[4], s4[4];
                ldm4(r4, sbase + G2B_HI + off);
                ldm4(s4, sbase + G2B_LO + off);
#pragma unroll
                for (int mi = 0; mi < 2; mi++) {
                    float* a0 = is_gate ? accg[mi][2 * p] : accm[mi][2 * p];
                    float* a1 = is_gate ? accg[mi][2 * p + 1] : accm[mi][2 * p + 1];
                    mma16816(a0, ah[mi], &r4[0]);
                    mma16816(a1, ah[mi], &r4[2]);
                    mma16816(a0, ah[mi], &s4[0]);
                    mma16816(a1, ah[mi], &s4[2]);
                    mma16816(a0, al[mi], &r4[0]);
                    mma16816(a1, al[mi], &r4[2]);
                }
            }
        }
        __syncthreads();
    }

    // fused epilogue: msg -> smem sagg (64 atoms x 64 cols) -> g_agg half
    float* sagg = (float*)sm;   // 16 KB, aliases stage
    for (int i = tid; i < AA * 64; i += 256) sagg[i] = 0.f;
    __syncthreads();

    int rl_base = wm * 32 + (lane >> 2);
    int c_loc = wn2 * 32 + (lane & 3) * 2;
#pragma unroll
    for (int mi = 0; mi < 2; mi++)
#pragma unroll
        for (int half = 0; half < 2; half++) {
            int rl = rl_base + mi * 16 + half * 8;
            int ld = sdst[rl];
#pragma unroll
            for (int nj = 0; nj < 4; nj++) {
                int col = c_loc + nj * 8;
                int gcol = nh * 64 + col;
                float v0 = fmaxf(accm[mi][nj][half * 2 + 0] + sbias[gcol], 0.f) *
                           accg[mi][nj][half * 2 + 0];
                float v1 = fmaxf(accm[mi][nj][half * 2 + 1] + sbias[gcol + 1], 0.f) *
                           accg[mi][nj][half * 2 + 1];
                atomicAdd(&sagg[ld * 64 + col], v0);
                atomicAdd(&sagg[ld * 64 + col + 1], v1);
            }
        }
    __syncthreads();

    size_t base = (size_t)(row0 / (AA * KNB)) * AA * HIDC + nh * 64;
    for (int i = tid; i < AA * 64; i += 256) {
        int r = i >> 6, cgl = i & 63;
        atomicAdd(&g_agg[base + (size_t)r * 128 + cgl], sagg[i]);
    }
}

// ---------------------------------------------------------------------------
extern "C" void kernel_launch(void* const* d_in, const int* in_sizes, int n_in,
                              void* d_out, int out_size) {
    const float* z        = (const float*)d_in[0];
    const float* frac     = (const float*)d_in[1];
    const float* lengths  = (const float*)d_in[2];
    const float* angles   = (const float*)d_in[3];
    const int*   atype    = (const int*)d_in[4];
    const int*   src      = (const int*)d_in[5];
    const int*   dst      = (const int*)d_in[6];
    const float* emb      = (const float*)d_in[7];
    const float* W_in     = (const float*)d_in[8];
    const float* b_in     = (const float*)d_in[9];
    const float* W_edge   = (const float*)d_in[10];
    const float* b_edge   = (const float*)d_in[11];
    const float* Wb_rbf   = (const float*)d_in[12];
    const float* Wb_msg   = (const float*)d_in[13];
    const float* bb_msg   = (const float*)d_in[14];
    const float* Wb_atom  = (const float*)d_in[15];
    const float* bb_atom  = (const float*)d_in[16];
    const float* Wb_upd   = (const float*)d_in[17];
    const float* bb_upd   = (const float*)d_in[18];
    const float* W_force  = (const float*)d_in[19];
    const float* b_force  = (const float*)d_in[20];
    const float* W_fc1    = (const float*)d_in[21];
    const float* b_fc1    = (const float*)d_in[22];
    const float* W_fc2    = (const float*)d_in[23];
    const float* b_fc2    = (const float*)d_in[24];
    const float* W_fc3    = (const float*)d_in[25];
    const float* b_fc3    = (const float*)d_in[26];
    float* out = (float*)d_out;

    float *pH, *pAgg;
    __nv_bfloat16 *pWhi, *pWlo, *pHhi, *pHlo;
    cudaGetSymbolAddress((void**)&pH,   g_h);
    cudaGetSymbolAddress((void**)&pAgg, g_agg);
    cudaGetSymbolAddress((void**)&pWhi, g_wt_hi);
    cudaGetSymbolAddress((void**)&pWlo, g_wt_lo);
    cudaGetSymbolAddress((void**)&pHhi, g_h_hi);
    cudaGetSymbolAddress((void**)&pHlo, g_h_lo);

    cudaFuncSetAttribute((const void*)mma_edge_gemm<2, 0>,
                         cudaFuncAttributeMaxDynamicSharedMemorySize, SMB_EDGE);
    cudaFuncSetAttribute((const void*)mma_edge_gemm<3, 0>,
                         cudaFuncAttributeMaxDynamicSharedMemorySize, SMB_EDGE);
    cudaFuncSetAttribute((const void*)mma_edge_gemm<3, 1>,
                         cudaFuncAttributeMaxDynamicSharedMemorySize, SMB_EDGE);
    cudaFuncSetAttribute((const void*)mma_gatemsg,
                         cudaFuncAttributeMaxDynamicSharedMemorySize, SMB_GM2);
    cudaFuncSetAttribute((const void*)fc_fused,
                         cudaFuncAttributeMaxDynamicSharedMemorySize, SMB_FC);

    geo_k<<<NCRYST, 256>>>(lengths, angles, frac, src, dst);
    wprep_all<<<1152, 256>>>(W_edge, Wb_rbf, Wb_msg, Wb_upd);

    gemm_k<1, 384, 1, 1, 0><<<NATOMS / 64, 256>>>(
        nullptr, W_in, b_in, nullptr, pH, pHhi, pHlo, nullptr, emb, z, atype);
    mma_edge_gemm<2, 0><<<NEDGE / 128, 256, SMB_EDGE>>>(
        pWhi + WOFF_EDGE, pWlo + WOFF_EDGE, b_edge, src, dst,
        nullptr, nullptr, nullptr);

    zero_agg_k<<<NATOMS * HIDC / 1024, 256>>>(out);
    for (int i = 0; i < 3; i++) {
        mma_gatemsg<<<NEDGE / 128 * 2, 256, SMB_GM2>>>(
            pWhi + WOFF_RBF + i * 16384, pWlo + WOFF_RBF + i * 16384,
            pWhi + WOFF_MSG + i * 16384, pWlo + WOFF_MSG + i * 16384,
            bb_msg + i * 128, dst);
        gemm_k<0, 128, 3, 1, 1><<<NATOMS / 64, 256>>>(
            pAgg, Wb_atom + (size_t)i * 16384, bb_atom + i * 128, pH, pH,
            pHhi, pHlo, pAgg, emb, z, atype);
        if (i < 2) {
            mma_edge_gemm<3, 0><<<NEDGE / 128, 256, SMB_EDGE>>>(
                pWhi + WOFF_UPD + i * 49152, pWlo + WOFF_UPD + i * 49152,
                bb_upd + i * 128, src, dst, nullptr, nullptr, nullptr);
        } else {
            mma_edge_gemm<3, 1><<<NEDGE / 128, 256, SMB_EDGE>>>(
                pWhi + WOFF_UPD + i * 49152, pWlo + WOFF_UPD + i * 49152,
                bb_upd + i * 128, src, dst, W_force, b_force, out);
        }
    }

    fc_fused<<<NATOMS / 64, 256, SMB_FC>>>(W_fc1, b_fc1, W_fc2, b_fc2,
                                           W_fc3, b_fc3,
                                           out + (size_t)NATOMS * 3);

    (void)in_sizes; (void)n_in; (void)out_size;
}

// round 16
// speedup vs baseline: 1.1312x; 1.1312x over previous
#include <cuda_runtime.h>
#include <cuda_bf16.h>
#include <cstdint>

// ---------------------------------------------------------------------------
// GemNetTDecoder — R16: R14 champion + gatemsg split along M (64 rows/CTA,
// full 128 cols) for 2 CTAs/SM. Duplicated fetch is only the L2-resident
// weight tile (R15's N-split wrongly duplicated the DRAM-resident m reads).
// ---------------------------------------------------------------------------

#define PI_F 3.14159265358979323846f

constexpr int NCRYST = 256;
constexpr int AA     = 64;
constexpr int KNB    = 20;
constexpr int HIDC   = 128;
constexpr int LATC   = 256;
constexpr int NATOMS = NCRYST * AA;       // 16384
constexpr int NEDGE  = NATOMS * KNB;      // 327680
constexpr float FCUT = 6.0f;
constexpr float DELTA = FCUT / 127.0f;

constexpr size_t EH = (size_t)NEDGE * HIDC;

constexpr int WOFF_EDGE = 0;
constexpr int WOFF_RBF  = 49152;
constexpr int WOFF_MSG  = 98304;
constexpr int WOFF_UPD  = 147456;
constexpr int WTOT      = 294912;

// --------------------------- device scratch -------------------------------
__device__ float g_dist[NEDGE];
__device__ float g_unit[NEDGE * 3];
__device__ float g_h[NATOMS * HIDC];
__device__ __nv_bfloat16 g_h_hi[NATOMS * HIDC];
__device__ __nv_bfloat16 g_h_lo[NATOMS * HIDC];
__device__ __nv_bfloat16 g_m_hi[EH];
__device__ __nv_bfloat16 g_m_lo[EH];
__device__ float g_agg[NATOMS * HIDC];
__device__ __nv_bfloat16 g_wt_hi[WTOT];
__device__ __nv_bfloat16 g_wt_lo[WTOT];

// --------------------------- helpers ---------------------------------------
__device__ __forceinline__ uint32_t smem_u32(const void* p) {
    uint32_t a;
    asm("{ .reg .u64 t; cvta.to.shared.u64 t, %1; cvt.u32.u64 %0, t; }"
        : "=r"(a) : "l"(p));
    return a;
}
__device__ __forceinline__ void ldm4(uint32_t* r, uint32_t a) {
    asm volatile("ldmatrix.sync.aligned.m8n8.x4.shared.b16 {%0,%1,%2,%3}, [%4];"
                 : "=r"(r[0]), "=r"(r[1]), "=r"(r[2]), "=r"(r[3]) : "r"(a));
}
__device__ __forceinline__ void mma16816(float* c, const uint32_t* a,
                                         const uint32_t* b) {
    asm volatile(
        "mma.sync.aligned.m16n8k16.row.col.f32.bf16.bf16.f32 "
        "{%0,%1,%2,%3}, {%4,%5,%6,%7}, {%8,%9}, {%0,%1,%2,%3};"
        : "+f"(c[0]), "+f"(c[1]), "+f"(c[2]), "+f"(c[3])
        : "r"(a[0]), "r"(a[1]), "r"(a[2]), "r"(a[3]), "r"(b[0]), "r"(b[1]));
}
__device__ __forceinline__ void cp16(uint32_t dst, const void* src) {
    asm volatile("cp.async.cg.shared.global [%0], [%1], 16;"
                 :: "r"(dst), "l"(src) : "memory");
}
__device__ __forceinline__ void cp_commit() {
    asm volatile("cp.async.commit_group;" ::: "memory");
}
__device__ __forceinline__ void cp_wait0() {
    asm volatile("cp.async.wait_group 0;" ::: "memory");
}
__device__ __forceinline__ uint32_t pack_bf(__nv_bfloat16 a, __nv_bfloat16 b) {
    return (uint32_t)__bfloat16_as_ushort(a) |
           ((uint32_t)__bfloat16_as_ushort(b) << 16);
}
__device__ __forceinline__ void split2(float v0, float v1, uint32_t& hi,
                                       uint32_t& lo) {
    __nv_bfloat16 h0 = __float2bfloat16(v0), h1 = __float2bfloat16(v1);
    hi = pack_bf(h0, h1);
    lo = pack_bf(__float2bfloat16(v0 - __bfloat162float(h0)),
                 __float2bfloat16(v1 - __bfloat162float(h1)));
}
__device__ __forceinline__ float bf2sum(uint32_t hi, uint32_t lo, int half) {
    uint16_t h = half ? (uint16_t)(hi >> 16) : (uint16_t)(hi & 0xffff);
    uint16_t l = half ? (uint16_t)(lo >> 16) : (uint16_t)(lo & 0xffff);
    return __bfloat162float(__ushort_as_bfloat16(h)) +
           __bfloat162float(__ushort_as_bfloat16(l));
}

constexpr int STR   = 72;
constexpr int TILEB = 128 * STR * 2;      // 18432

// ---- edge gemm smem geometry (R14, unchanged) ----
constexpr int EA4_HI = 0;
constexpr int EA4_LO = TILEB;
constexpr int EA5_HI = 2 * TILEB;
constexpr int EA5_LO = 3 * TILEB;
constexpr int EB_HI  = 4 * TILEB;
constexpr int EB_LO  = 5 * TILEB;
constexpr int EEND   = 6 * TILEB;
constexpr int E_BIAS = EEND;
constexpr int E_SRC  = E_BIAS + 512;
constexpr int E_DST  = E_SRC + 512;
constexpr int E_DIST = E_DST + 512;
constexpr int E_WF   = E_DIST + 512;
constexpr int E_FRC  = E_WF + 512;
constexpr int SMB_EDGE = E_FRC + 512;     // 113664

// ---- gatemsg (M-split) smem: A 64x64 hi/lo, B 128x64 hi/lo, single stage ----
constexpr int G3A_HI = 0;                 // 64 x 144 = 9216
constexpr int G3A_LO = 9216;
constexpr int G3B_HI = 18432;             // 128 x 144 = 18432
constexpr int G3B_LO = 36864;
constexpr int G3END  = 55296;
constexpr int G3_BIAS = G3END;
constexpr int G3_DST  = G3_BIAS + 512;
constexpr int G3_DIST = G3_DST + 512;
constexpr int SMB_GM3 = G3_DIST + 512;    // 56832 (2 CTAs/SM: 113664)

// ---- fc_fused smem geometry ----
constexpr int F_XS = 0;
constexpr int F_WS = 4352;
constexpr int F_A1 = 12544;
constexpr int F_A2 = 46336;
constexpr int SMB_FC = 80128;

// Generate rbf tile (cols [kc2, kc2+64)) into 128-row smem hi/lo planes.
__device__ __forceinline__ void gen_rbf(char* smp, int off_hi, int off_lo,
                                        const float* sdist, int kc2, int tid) {
    uint4 z4 = make_uint4(0, 0, 0, 0);
#pragma unroll
    for (int i = 0; i < 9; i++) {
        int lin = i * 256 + tid;
        if (lin < 2304) {
            int plane = lin >= 1152;
            int j = plane ? lin - 1152 : lin;
            *(uint4*)(smp + (plane ? off_lo : off_hi) + j * 16) = z4;
        }
    }
    __syncthreads();
    if (tid < 128) {
        float d = sdist[tid];
        if (d < FCUT) {
            float env = 0.5f * (cosf(PI_F * d * (1.f / FCUT)) + 1.f);
            float t = d * (1.f / DELTA);
            int klo = max(kc2, (int)ceilf(t) - 6);
            int khi = min(kc2 + 63, (int)floorf(t) + 6);
            for (int k = klo; k <= khi; k++) {
                float x = t - (float)k;
                float v = __expf(-x * x) * env;
                __nv_bfloat16 h = __float2bfloat16(v);
                __nv_bfloat16 l = __float2bfloat16(v - __bfloat162float(h));
                int boff = tid * 144 + (k - kc2) * 2;
                *(__nv_bfloat16*)(smp + off_hi + boff) = h;
                *(__nv_bfloat16*)(smp + off_lo + boff) = l;
            }
        }
    }
}

// 64-row variant for the M-split gatemsg (planes at G3A_HI/G3A_LO).
__device__ __forceinline__ void gen_rbf64(char* smp, const float* sdist,
                                          int kc2, int tid) {
    uint4 z4 = make_uint4(0, 0, 0, 0);
#pragma unroll
    for (int i = 0; i < 5; i++) {
        int lin = i * 256 + tid;
        if (lin < 1152) *(uint4*)(smp + lin * 16) = z4;   // A_HI+A_LO contiguous
    }
    __syncthreads();
    if (tid < 64) {
        float d = sdist[tid];
        if (d < FCUT) {
            float env = 0.5f * (cosf(PI_F * d * (1.f / FCUT)) + 1.f);
            float t = d * (1.f / DELTA);
            int klo = max(kc2, (int)ceilf(t) - 6);
            int khi = min(kc2 + 63, (int)floorf(t) + 6);
            for (int k = klo; k <= khi; k++) {
                float x = t - (float)k;
                float v = __expf(-x * x) * env;
                __nv_bfloat16 h = __float2bfloat16(v);
                __nv_bfloat16 l = __float2bfloat16(v - __bfloat162float(h));
                int boff = tid * 144 + (k - kc2) * 2;
                *(__nv_bfloat16*)(smp + G3A_HI + boff) = h;
                *(__nv_bfloat16*)(smp + G3A_LO + boff) = l;
            }
        }
    }
}

// --------------------------- fused geometry --------------------------------
__global__ __launch_bounds__(256) void geo_k(
    const float* __restrict__ lengths, const float* __restrict__ angles,
    const float* __restrict__ frac, const int* __restrict__ src,
    const int* __restrict__ dst) {
    __shared__ float sc[AA][3];
    int c = blockIdx.x, tid = threadIdx.x;
    float r0 = angles[c * 3 + 0] * (PI_F / 180.f);
    float r1 = angles[c * 3 + 1] * (PI_F / 180.f);
    float r2 = angles[c * 3 + 2] * (PI_F / 180.f);
    float c0 = cosf(r0), c1 = cosf(r1), c2 = cosf(r2), sg = sinf(r2);
    float a = lengths[c * 3 + 0], b = lengths[c * 3 + 1], cc = lengths[c * 3 + 2];
    float cx = cc * c1;
    float cy = cc * (c0 - c1 * c2) / sg;
    float cz = sqrtf(fmaxf(cc * cc - cx * cx - cy * cy, 1e-8f));
    if (tid < AA) {
        int atom = c * AA + tid;
        float f0 = frac[atom * 3 + 0], f1 = frac[atom * 3 + 1],
              f2 = frac[atom * 3 + 2];
        sc[tid][0] = f0 * a + f1 * (b * c2) + f2 * cx;
        sc[tid][1] = f1 * (b * sg) + f2 * cy;
        sc[tid][2] = f2 * cz;
    }
    __syncthreads();
#pragma unroll
    for (int i = 0; i < 5; i++) {
        int el = i * 256 + tid;
        int e = c * (AA * KNB) + el;
        int s = src[e] & 63, d = dst[e] & 63;
        float dx = sc[d][0] - sc[s][0];
        float dy = sc[d][1] - sc[s][1];
        float dz = sc[d][2] - sc[s][2];
        float dist = sqrtf(dx * dx + dy * dy + dz * dz + 1e-12f);
        g_dist[e] = dist;
        float inv = 1.f / dist;
        g_unit[e * 3 + 0] = dx * inv;
        g_unit[e * 3 + 1] = dy * inv;
        g_unit[e * 3 + 2] = dz * inv;
    }
}

// --------------------------- merged weight prep ----------------------------
__global__ __launch_bounds__(256) void wprep_all(
    const float* __restrict__ We, const float* __restrict__ Wr,
    const float* __restrict__ Wm, const float* __restrict__ Wu) {
    int blk = blockIdx.x;
    const float* W;
    int K, base, lb;
    if (blk < 192)      { W = We; K = 384; base = WOFF_EDGE; lb = blk; }
    else if (blk < 384) { W = Wr; K = 128; base = WOFF_RBF;  lb = blk - 192; }
    else if (blk < 576) { W = Wm; K = 128; base = WOFF_MSG;  lb = blk - 384; }
    else                { W = Wu; K = 384; base = WOFF_UPD;  lb = blk - 576; }
    int idx = lb * 256 + threadIdx.x;
    int m = idx / (K * 128);
    int r = idx - m * (K * 128);
    int k = r >> 7, n = r & 127;
    float v = W[idx];
    __nv_bfloat16 h = __float2bfloat16(v);
    size_t o = (size_t)base + (size_t)m * K * 128 + (size_t)n * K + k;
    g_wt_hi[o] = h;
    g_wt_lo[o] = __float2bfloat16(v - __bfloat162float(h));
}

__global__ void zero_agg_k(float* __restrict__ outp) {
    int i = blockIdx.x * 256 + threadIdx.x;
    *(float4*)&g_agg[(size_t)i * 4] = make_float4(0.f, 0.f, 0.f, 0.f);
    if (i * 4 < NATOMS * 3)
        *(float4*)&outp[(size_t)i * 4] = make_float4(0.f, 0.f, 0.f, 0.f);
}

// --------------------------- fp32 SIMT gemm (small) ------------------------
template <int MODE, int KDIM, int EPI, int SPLIT, int ZAGG>
__global__ __launch_bounds__(256) void gemm_k(
    const float* __restrict__ X, const float* __restrict__ W,
    const float* __restrict__ bias, const float* __restrict__ base,
    float* __restrict__ out, __nv_bfloat16* __restrict__ outhi,
    __nv_bfloat16* __restrict__ outlo, float* __restrict__ zbuf,
    const float* __restrict__ emb, const float* __restrict__ z,
    const int* __restrict__ atype) {
    __shared__ float Xs[16][68];
    __shared__ float Ws[16][128];
    __shared__ int sat[64];

    int row0 = blockIdx.x * 64;
    int tid = threadIdx.x;
    if (MODE == 1) {
        if (tid < 64) sat[tid] = atype[row0 + tid];
        __syncthreads();
    }

    int c0 = (tid & 15) * 8;
    int r0 = (tid >> 4) * 4;
    float acc[4][8];
#pragma unroll
    for (int i = 0; i < 4; i++)
#pragma unroll
        for (int j = 0; j < 8; j++) acc[i][j] = 0.f;

    for (int k0 = 0; k0 < KDIM; k0 += 16) {
#pragma unroll
        for (int t = 0; t < 4; t++) {
            int lin = tid * 4 + t;
            int r = lin >> 4, kk = lin & 15;
            int k = k0 + kk;
            float v;
            if (MODE == 0) {
                v = X[(size_t)(row0 + r) * KDIM + k];
            } else {
                v = (k < 128) ? emb[sat[r] * 128 + k]
                              : z[(size_t)((row0 + r) >> 6) * LATC + (k - 128)];
            }
            Xs[kk][r] = v;
        }
#pragma unroll
        for (int t = 0; t < 2; t++) {
            int i4 = tid + t * 256;
            int kk = i4 >> 5, n = (i4 & 31) * 4;
            *(float4*)&Ws[kk][n] = *(const float4*)&W[(size_t)(k0 + kk) * 128 + n];
        }
        __syncthreads();
#pragma unroll
        for (int kk = 0; kk < 16; kk++) {
            float4 a  = *(const float4*)&Xs[kk][r0];
            float4 b0 = *(const float4*)&Ws[kk][c0];
            float4 b1 = *(const float4*)&Ws[kk][c0 + 4];
            float av[4] = {a.x, a.y, a.z, a.w};
            float bv[8] = {b0.x, b0.y, b0.z, b0.w, b1.x, b1.y, b1.z, b1.w};
#pragma unroll
            for (int i = 0; i < 4; i++)
#pragma unroll
                for (int j = 0; j < 8; j++) acc[i][j] += av[i] * bv[j];
        }
        __syncthreads();
    }

    float bv[8];
    {
        float4 q0 = *(const float4*)&bias[c0];
        float4 q1 = *(const float4*)&bias[c0 + 4];
        bv[0] = q0.x; bv[1] = q0.y; bv[2] = q0.z; bv[3] = q0.w;
        bv[4] = q1.x; bv[5] = q1.y; bv[6] = q1.z; bv[7] = q1.w;
    }
#pragma unroll
    for (int i = 0; i < 4; i++) {
        size_t off = (size_t)(row0 + r0 + i) * 128 + c0;
        float v[8];
#pragma unroll
        for (int j = 0; j < 8; j++) v[j] = fmaxf(acc[i][j] + bv[j], 0.f);
        if (EPI == 3) {
            float4 bb0 = *(const float4*)&base[off];
            float4 bb1 = *(const float4*)&base[off + 4];
            v[0] += bb0.x; v[1] += bb0.y; v[2] += bb0.z; v[3] += bb0.w;
            v[4] += bb1.x; v[5] += bb1.y; v[6] += bb1.z; v[7] += bb1.w;
        }
        float4 o0 = {v[0], v[1], v[2], v[3]};
        float4 o1 = {v[4], v[5], v[6], v[7]};
        *(float4*)&out[off] = o0;
        *(float4*)&out[off + 4] = o1;
        if (SPLIT) {
            uint32_t hh[4], ll[4];
#pragma unroll
            for (int q = 0; q < 4; q++) split2(v[2 * q], v[2 * q + 1], hh[q], ll[q]);
            *(uint4*)&outhi[off] = make_uint4(hh[0], hh[1], hh[2], hh[3]);
            *(uint4*)&outlo[off] = make_uint4(ll[0], ll[1], ll[2], ll[3]);
        }
        if (ZAGG) {
            float4 zz = {0.f, 0.f, 0.f, 0.f};
            *(float4*)&zbuf[off] = zz;
            *(float4*)&zbuf[off + 4] = zz;
        }
    }
}

// --------------------------- fused fc1+fc2+fc3 -----------------------------
__global__ __launch_bounds__(256) void fc_fused(
    const float* __restrict__ W1, const float* __restrict__ b1,
    const float* __restrict__ W2, const float* __restrict__ b2,
    const float* __restrict__ W3, const float* __restrict__ b3,
    float* __restrict__ out) {
    extern __shared__ char sm[];
    float (*Xs)[68]  = (float(*)[68])(sm + F_XS);
    float (*Ws)[128] = (float(*)[128])(sm + F_WS);
    float* A1 = (float*)(sm + F_A1);
    float* A2 = (float*)(sm + F_A2);

    int row0 = blockIdx.x * 64;
    int tid = threadIdx.x;
    int c0 = (tid & 15) * 8;
    int r0 = (tid >> 4) * 4;

#pragma unroll
    for (int phase = 0; phase < 2; phase++) {
        const float* W = phase ? W2 : W1;
        const float* bias = phase ? b2 : b1;
        float* dstA = phase ? A2 : A1;
        float acc[4][8];
#pragma unroll
        for (int i = 0; i < 4; i++)
#pragma unroll
            for (int j = 0; j < 8; j++) acc[i][j] = 0.f;
        for (int k0 = 0; k0 < 128; k0 += 16) {
#pragma unroll
            for (int t = 0; t < 4; t++) {
                int lin = tid * 4 + t;
                int r = lin >> 4, kk = lin & 15;
                float v = phase ? A1[r * 132 + k0 + kk]
                                : g_h[(size_t)(row0 + r) * 128 + k0 + kk];
                Xs[kk][r] = v;
            }
#pragma unroll
            for (int t = 0; t < 2; t++) {
                int i4 = tid + t * 256;
                int kk = i4 >> 5, n = (i4 & 31) * 4;
                *(float4*)&Ws[kk][n] =
                    *(const float4*)&W[(size_t)(k0 + kk) * 128 + n];
            }
            __syncthreads();
#pragma unroll
            for (int kk = 0; kk < 16; kk++) {
                float4 a  = *(const float4*)&Xs[kk][r0];
                float4 b0 = *(const float4*)&Ws[kk][c0];
                float4 b1v = *(const float4*)&Ws[kk][c0 + 4];
                float av[4] = {a.x, a.y, a.z, a.w};
                float bv[8] = {b0.x, b0.y, b0.z, b0.w, b1v.x, b1v.y, b1v.z, b1v.w};
#pragma unroll
                for (int i = 0; i < 4; i++)
#pragma unroll
                    for (int j = 0; j < 8; j++) acc[i][j] += av[i] * bv[j];
            }
            __syncthreads();
        }
        float bv[8];
        {
            float4 q0 = *(const float4*)&bias[c0];
            float4 q1 = *(const float4*)&bias[c0 + 4];
            bv[0] = q0.x; bv[1] = q0.y; bv[2] = q0.z; bv[3] = q0.w;
            bv[4] = q1.x; bv[5] = q1.y; bv[6] = q1.z; bv[7] = q1.w;
        }
#pragma unroll
        for (int i = 0; i < 4; i++)
#pragma unroll
            for (int j = 0; j < 8; j++)
                dstA[(r0 + i) * 132 + c0 + j] = fmaxf(acc[i][j] + bv[j], 0.f);
        __syncthreads();
    }

    if (tid < 128) {
        int row = tid >> 1;
        int col = tid & 1;
        float s = 0.f;
#pragma unroll 16
        for (int k = 0; k < 128; k++) s += A2[row * 132 + k] * W3[k * 2 + col];
        out[(size_t)(row0 + row) * 2 + col] = s + b3[col];
    }
}

// --------------------------- mma.sync edge GEMM (R14, unchanged) -----------
template <int MODE, int FORCE>
__global__ __launch_bounds__(256, 2) void mma_edge_gemm(
    const __nv_bfloat16* __restrict__ wt_hi, const __nv_bfloat16* __restrict__ wt_lo,
    const float* __restrict__ bias, const int* __restrict__ srcp,
    const int* __restrict__ dstp, const float* __restrict__ Wf,
    const float* __restrict__ bf, float* __restrict__ outp) {
    extern __shared__ char sm[];
    uint32_t sbase = smem_u32(sm);
    float* sbias = (float*)(sm + E_BIAS);
    int* ssrc = (int*)(sm + E_SRC);
    int* sdst = (int*)(sm + E_DST);
    float* sdist = (float*)(sm + E_DIST);
    float* sWf = (float*)(sm + E_WF);
    float* sfrc = (float*)(sm + E_FRC);

    int tid = threadIdx.x;
    int row0 = blockIdx.x * 128;
    if (tid < 128) {
        ssrc[tid] = srcp[row0 + tid];
        sdst[tid] = dstp[row0 + tid];
        sbias[tid] = bias[tid];
        if (MODE == 2) sdist[tid] = g_dist[row0 + tid];
        if (FORCE) { sWf[tid] = Wf[tid]; sfrc[tid] = 0.f; }
    }
    __syncthreads();

    auto prefetch = [&](int c) {
        int kc = c * 64;
        int a_hi = (c == 5) ? EA5_HI : EA4_HI;
        int a_lo = (c == 5) ? EA5_LO : EA4_LO;
#pragma unroll
        for (int i = 0; i < 8; i++) {
            int lin = i * 256 + tid;
            int plane = lin >> 10;
            int idx = lin & 1023;
            int row = idx >> 3;
            int seg = idx & 7;
            if (!(MODE == 2 && c >= 4)) {
                const __nv_bfloat16* ap;
                if (c >= 4) {
                    ap = (plane ? g_m_lo : g_m_hi) +
                         (size_t)(row0 + row) * 128 + (kc - 256) + seg * 8;
                } else if (c < 2) {
                    ap = (plane ? g_h_lo : g_h_hi) + (size_t)ssrc[row] * 128 +
                         kc + seg * 8;
                } else {
                    ap = (plane ? g_h_lo : g_h_hi) + (size_t)sdst[row] * 128 +
                         (kc - 128) + seg * 8;
                }
                cp16(sbase + (plane ? a_lo : a_hi) + row * 144 + seg * 16, ap);
            }
            const __nv_bfloat16* bp =
                (plane ? wt_lo : wt_hi) + (size_t)row * 384 + kc + seg * 8;
            cp16(sbase + (plane ? EB_LO : EB_HI) + row * 144 + seg * 16, bp);
        }
        cp_commit();
    };

    int lane = tid & 31;
    int wm = (tid >> 5) & 3;
    int wn = tid >> 7;
    uint32_t a_row_l = (lane & 7) + ((lane >> 3) & 1) * 8;
    uint32_t a_k_l   = (lane >> 4) * 8;
    uint32_t b_n_l   = (lane & 7) + ((lane >> 4) & 1) * 8;
    uint32_t b_k_l   = ((lane >> 3) & 1) * 8;

    float acc[2][8][4];
#pragma unroll
    for (int i = 0; i < 2; i++)
#pragma unroll
        for (int j = 0; j < 8; j++)
#pragma unroll
            for (int q = 0; q < 4; q++) acc[i][j][q] = 0.f;

    for (int c = 0; c < 6; c++) {
        prefetch(c);
        if (MODE == 2 && c >= 4)
            gen_rbf(sm, (c == 5) ? EA5_HI : EA4_HI, (c == 5) ? EA5_LO : EA4_LO,
                    sdist, (c - 4) * 64, tid);
        cp_wait0();
        __syncthreads();
        uint32_t a_hi = sbase + ((c == 5) ? EA5_HI : EA4_HI);
        uint32_t a_lo = sbase + ((c == 5) ? EA5_LO : EA4_LO);
#pragma unroll
        for (int k16 = 0; k16 < 4; k16++) {
            uint32_t kk = k16 * 16;
            uint32_t ah[2][4], al[2][4];
#pragma unroll
            for (int mi = 0; mi < 2; mi++) {
                uint32_t off = (((uint32_t)(wm * 32 + mi * 16) + a_row_l) * STR +
                                kk + a_k_l) * 2;
                ldm4(ah[mi], a_hi + off);
                ldm4(al[mi], a_lo + off);
            }
#pragma unroll
            for (int p = 0; p < 4; p++) {
                uint32_t off = (((uint32_t)(wn * 64 + p * 16) + b_n_l) * STR +
                                kk + b_k_l) * 2;
                uint32_t r4[4], s4[4];
                ldm4(r4, sbase + EB_HI + off);
                ldm4(s4, sbase + EB_LO + off);
#pragma unroll
                for (int mi = 0; mi < 2; mi++) {
                    mma16816(acc[mi][2 * p],     ah[mi], &r4[0]);
                    mma16816(acc[mi][2 * p + 1], ah[mi], &r4[2]);
                    mma16816(acc[mi][2 * p],     ah[mi], &s4[0]);
                    mma16816(acc[mi][2 * p + 1], ah[mi], &s4[2]);
                    mma16816(acc[mi][2 * p],     al[mi], &r4[0]);
                    mma16816(acc[mi][2 * p + 1], al[mi], &r4[2]);
                }
            }
        }
        __syncthreads();
    }

    int rl_base = wm * 32 + (lane >> 2);
    int c_base = wn * 64 + (lane & 3) * 2;
    int resid_hi = wn ? EA5_HI : EA4_HI;
    int resid_lo = wn ? EA5_LO : EA4_LO;
    float rowpart[4] = {0.f, 0.f, 0.f, 0.f};
#pragma unroll
    for (int mi = 0; mi < 2; mi++)
#pragma unroll
        for (int nj = 0; nj < 8; nj++) {
            int rl = rl_base + mi * 16;
            int col = c_base + nj * 8;
            int lcol = col - wn * 64;
            float2 bb = *(const float2*)&sbias[col];
#pragma unroll
            for (int half = 0; half < 2; half++) {
                int row = rl + half * 8;
                size_t off = (size_t)(row0 + row) * 128 + col;
                float v0 = fmaxf(acc[mi][nj][half * 2 + 0] + bb.x, 0.f);
                float v1 = fmaxf(acc[mi][nj][half * 2 + 1] + bb.y, 0.f);
                if (MODE == 3) {
                    uint32_t oh = *(const uint32_t*)(sm + resid_hi +
                                                     row * 144 + lcol * 2);
                    uint32_t ol = *(const uint32_t*)(sm + resid_lo +
                                                     row * 144 + lcol * 2);
                    v0 += bf2sum(oh, ol, 0);
                    v1 += bf2sum(oh, ol, 1);
                }
                if (FORCE) {
                    rowpart[mi * 2 + half] += v0 * sWf[col] + v1 * sWf[col + 1];
                } else {
                    uint32_t hh, ll;
                    split2(v0, v1, hh, ll);
                    *(uint32_t*)&g_m_hi[off] = hh;
                    *(uint32_t*)&g_m_lo[off] = ll;
                }
            }
        }
    if (FORCE) {
#pragma unroll
        for (int q = 0; q < 4; q++) {
            int row = rl_base + (q >> 1) * 16 + (q & 1) * 8;
            atomicAdd(&sfrc[row], rowpart[q]);
        }
        __syncthreads();
        if (tid < 128) {
            float f = sfrc[tid] + bf[0];
            int d = sdst[tid];
            size_t ub = (size_t)(row0 + tid) * 3;
            atomicAdd(&outp[d * 3 + 0], f * g_unit[ub + 0]);
            atomicAdd(&outp[d * 3 + 1], f * g_unit[ub + 1]);
            atomicAdd(&outp[d * 3 + 2], f * g_unit[ub + 2]);
        }
    }
}

// --------------------------- gate*msg + segsum, M-split, 2 CTAs/SM ---------
// blockIdx.x = 64-row block; CTA computes rows [row0, row0+64) x all 128 cols.
__global__ __launch_bounds__(256, 2) void mma_gatemsg(
    const __nv_bfloat16* __restrict__ wrbf_hi, const __nv_bfloat16* __restrict__ wrbf_lo,
    const __nv_bfloat16* __restrict__ wmsg_hi, const __nv_bfloat16* __restrict__ wmsg_lo,
    const float* __restrict__ bias, const int* __restrict__ dstp) {
    extern __shared__ char sm[];
    uint32_t sbase = smem_u32(sm);
    float* sbias = (float*)(sm + G3_BIAS);
    int* sdst = (int*)(sm + G3_DST);
    float* sdist = (float*)(sm + G3_DIST);

    int tid = threadIdx.x;
    int row0 = blockIdx.x * 64;
    if (tid < 128) sbias[tid] = bias[tid];
    if (tid < 64) {
        sdst[tid] = dstp[row0 + tid] & 63;
        sdist[tid] = g_dist[row0 + tid];
    }
    __syncthreads();

    auto prefetch = [&](int c) {
        bool is_gate = (c < 2);
        int kc = (c & 1) * 64;
        const __nv_bfloat16* whi = is_gate ? wrbf_hi : wmsg_hi;
        const __nv_bfloat16* wlo = is_gate ? wrbf_lo : wmsg_lo;
        // B: 128 N-rows x 64 K hi/lo -> 2048 cp16
#pragma unroll
        for (int i = 0; i < 8; i++) {
            int lin = i * 256 + tid;
            int plane = lin >> 10;
            int idx = lin & 1023;
            int n = idx >> 3;
            int seg = idx & 7;
            const __nv_bfloat16* bp =
                (plane ? wlo : whi) + (size_t)n * 128 + kc + seg * 8;
            cp16(sbase + (plane ? G3B_LO : G3B_HI) + n * 144 + seg * 16, bp);
        }
        if (!is_gate) {
            // A: 64 rows x 64 K hi/lo -> 1024 cp16
#pragma unroll
            for (int i = 0; i < 4; i++) {
                int lin = i * 256 + tid;
                int plane = lin >> 9;
                int idx = lin & 511;
                int row = idx >> 3;
                int seg = idx & 7;
                const __nv_bfloat16* ap =
                    (plane ? g_m_lo : g_m_hi) + (size_t)(row0 + row) * 128 +
                    kc + seg * 8;
                cp16(sbase + (plane ? G3A_LO : G3A_HI) + row * 144 + seg * 16, ap);
            }
        }
        cp_commit();
    };

    int lane = tid & 31;
    int w = tid >> 5;
    int wm = w & 1;            // 2 M blocks of 32 rows
    int wn = w >> 1;           // 4 N blocks of 32 cols
    uint32_t a_row_l = (lane & 7) + ((lane >> 3) & 1) * 8;
    uint32_t a_k_l   = (lane >> 4) * 8;
    uint32_t b_n_l   = (lane & 7) + ((lane >> 4) & 1) * 8;
    uint32_t b_k_l   = ((lane >> 3) & 1) * 8;

    float accg[2][4][4], accm[2][4][4];
#pragma unroll
    for (int i = 0; i < 2; i++)
#pragma unroll
        for (int j = 0; j < 4; j++)
#pragma unroll
            for (int q = 0; q < 4; q++) { accg[i][j][q] = 0.f; accm[i][j][q] = 0.f; }

    for (int c = 0; c < 4; c++) {
        bool is_gate = (c < 2);
        prefetch(c);
        if (is_gate)
            gen_rbf64(sm, sdist, (c & 1) * 64, tid);
        cp_wait0();
        __syncthreads();
#pragma unroll
        for (int k16 = 0; k16 < 4; k16++) {
            uint32_t kk = k16 * 16;
            uint32_t ah[2][4], al[2][4];
#pragma unroll
            for (int mi = 0; mi < 2; mi++) {
                uint32_t off = (((uint32_t)(wm * 32 + mi * 16) + a_row_l) * STR +
                                kk + a_k_l) * 2;
                ldm4(ah[mi], sbase + G3A_HI + off);
                ldm4(al[mi], sbase + G3A_LO + off);
            }
#pragma unroll
            for (int p = 0; p < 2; p++) {
                uint32_t off = (((uint32_t)(wn * 32 + p * 16) + b_n_l) * STR +
                                kk + b_k_l) * 2;
                uint32_t r4[4], s4[4];
                ldm4(r4, sbase + G3B_HI + off);
                ldm4(s4, sbase + G3B_LO + off);
#pragma unroll
                for (int mi = 0; mi < 2; mi++) {
                    float* a0 = is_gate ? accg[mi][2 * p] : accm[mi][2 * p];
                    float* a1 = is_gate ? accg[mi][2 * p + 1] : accm[mi][2 * p + 1];
                    mma16816(a0, ah[mi], &r4[0]);
                    mma16816(a1, ah[mi], &r4[2]);
                    mma16816(a0, ah[mi], &s4[0]);
                    mma16816(a1, ah[mi], &s4[2]);
                    mma16816(a0, al[mi], &r4[0]);
                    mma16816(a1, al[mi], &r4[2]);
                }
            }
        }
        __syncthreads();
    }

    // fused epilogue: msg -> smem sagg (64 atoms x 128 cols) -> g_agg
    float* sagg = (float*)sm;   // 32 KB, aliases stage
    for (int i = tid; i < AA * HIDC; i += 256) sagg[i] = 0.f;
    __syncthreads();

    int rl_base = wm * 32 + (lane >> 2);
    int c_loc = wn * 32 + (lane & 3) * 2;
#pragma unroll
    for (int mi = 0; mi < 2; mi++)
#pragma unroll
        for (int half = 0; half < 2; half++) {
            int rl = rl_base + mi * 16 + half * 8;
            int ld = sdst[rl];
#pragma unroll
            for (int nj = 0; nj < 4; nj++) {
                int col = c_loc + nj * 8;
                float v0 = fmaxf(accm[mi][nj][half * 2 + 0] + sbias[col], 0.f) *
                           accg[mi][nj][half * 2 + 0];
                float v1 = fmaxf(accm[mi][nj][half * 2 + 1] + sbias[col + 1], 0.f) *
                           accg[mi][nj][half * 2 + 1];
                atomicAdd(&sagg[ld * 128 + col], v0);
                atomicAdd(&sagg[ld * 128 + col + 1], v1);
            }
        }
    __syncthreads();

    size_t base = (size_t)(row0 / (AA * KNB)) * AA * HIDC;
    for (int i = tid; i < AA * HIDC; i += 256)
        atomicAdd(&g_agg[base + i], sagg[i]);
}

// ---------------------------------------------------------------------------
extern "C" void kernel_launch(void* const* d_in, const int* in_sizes, int n_in,
                              void* d_out, int out_size) {
    const float* z        = (const float*)d_in[0];
    const float* frac     = (const float*)d_in[1];
    const float* lengths  = (const float*)d_in[2];
    const float* angles   = (const float*)d_in[3];
    const int*   atype    = (const int*)d_in[4];
    const int*   src      = (const int*)d_in[5];
    const int*   dst      = (const int*)d_in[6];
    const float* emb      = (const float*)d_in[7];
    const float* W_in     = (const float*)d_in[8];
    const float* b_in     = (const float*)d_in[9];
    const float* W_edge   = (const float*)d_in[10];
    const float* b_edge   = (const float*)d_in[11];
    const float* Wb_rbf   = (const float*)d_in[12];
    const float* Wb_msg   = (const float*)d_in[13];
    const float* bb_msg   = (const float*)d_in[14];
    const float* Wb_atom  = (const float*)d_in[15];
    const float* bb_atom  = (const float*)d_in[16];
    const float* Wb_upd   = (const float*)d_in[17];
    const float* bb_upd   = (const float*)d_in[18];
    const float* W_force  = (const float*)d_in[19];
    const float* b_force  = (const float*)d_in[20];
    const float* W_fc1    = (const float*)d_in[21];
    const float* b_fc1    = (const float*)d_in[22];
    const float* W_fc2    = (const float*)d_in[23];
    const float* b_fc2    = (const float*)d_in[24];
    const float* W_fc3    = (const float*)d_in[25];
    const float* b_fc3    = (const float*)d_in[26];
    float* out = (float*)d_out;

    float *pH, *pAgg;
    __nv_bfloat16 *pWhi, *pWlo, *pHhi, *pHlo;
    cudaGetSymbolAddress((void**)&pH,   g_h);
    cudaGetSymbolAddress((void**)&pAgg, g_agg);
    cudaGetSymbolAddress((void**)&pWhi, g_wt_hi);
    cudaGetSymbolAddress((void**)&pWlo, g_wt_lo);
    cudaGetSymbolAddress((void**)&pHhi, g_h_hi);
    cudaGetSymbolAddress((void**)&pHlo, g_h_lo);

    cudaFuncSetAttribute((const void*)mma_edge_gemm<2, 0>,
                         cudaFuncAttributeMaxDynamicSharedMemorySize, SMB_EDGE);
    cudaFuncSetAttribute((const void*)mma_edge_gemm<3, 0>,
                         cudaFuncAttributeMaxDynamicSharedMemorySize, SMB_EDGE);
    cudaFuncSetAttribute((const void*)mma_edge_gemm<3, 1>,
                         cudaFuncAttributeMaxDynamicSharedMemorySize, SMB_EDGE);
    cudaFuncSetAttribute((const void*)mma_gatemsg,
                         cudaFuncAttributeMaxDynamicSharedMemorySize, SMB_GM3);
    cudaFuncSetAttribute((const void*)fc_fused,
                         cudaFuncAttributeMaxDynamicSharedMemorySize, SMB_FC);

    geo_k<<<NCRYST, 256>>>(lengths, angles, frac, src, dst);
    wprep_all<<<1152, 256>>>(W_edge, Wb_rbf, Wb_msg, Wb_upd);

    gemm_k<1, 384, 1, 1, 0><<<NATOMS / 64, 256>>>(
        nullptr, W_in, b_in, nullptr, pH, pHhi, pHlo, nullptr, emb, z, atype);
    mma_edge_gemm<2, 0><<<NEDGE / 128, 256, SMB_EDGE>>>(
        pWhi + WOFF_EDGE, pWlo + WOFF_EDGE, b_edge, src, dst,
        nullptr, nullptr, nullptr);

    zero_agg_k<<<NATOMS * HIDC / 1024, 256>>>(out);
    for (int i = 0; i < 3; i++) {
        mma_gatemsg<<<NEDGE / 64, 256, SMB_GM3>>>(
            pWhi + WOFF_RBF + i * 16384, pWlo + WOFF_RBF + i * 16384,
            pWhi + WOFF_MSG + i * 16384, pWlo + WOFF_MSG + i * 16384,
            bb_msg + i * 128, dst);
        gemm_k<0, 128, 3, 1, 1><<<NATOMS / 64, 256>>>(
            pAgg, Wb_atom + (size_t)i * 16384, bb_atom + i * 128, pH, pH,
            pHhi, pHlo, pAgg, emb, z, atype);
        if (i < 2) {
            mma_edge_gemm<3, 0><<<NEDGE / 128, 256, SMB_EDGE>>>(
                pWhi + WOFF_UPD + i * 49152, pWlo + WOFF_UPD + i * 49152,
                bb_upd + i * 128, src, dst, nullptr, nullptr, nullptr);
        } else {
            mma_edge_gemm<3, 1><<<NEDGE / 128, 256, SMB_EDGE>>>(
                pWhi + WOFF_UPD + i * 49152, pWlo + WOFF_UPD + i * 49152,
                bb_upd + i * 128, src, dst, W_force, b_force, out);
        }
    }

    fc_fused<<<NATOMS / 64, 256, SMB_FC>>>(W_fc1, b_fc1, W_fc2, b_fc2,
                                           W_fc3, b_fc3,
                                           out + (size_t)NATOMS * 3);

    (void)in_sizes; (void)n_in; (void)out_size;
}